// round 5
// baseline (speedup 1.0000x reference)
#include <cuda_runtime.h>
#include <math.h>

// RMSD (Kabsch-aligned MSE), fused single kernel.
// cp.async (LDGSTS) gmem->smem pipelined 3 deep, quarter-batch stages.
// One warp per batch; conflict-free LDS.32 compute; last-block final reduce.

constexpr int NB    = 8192;
constexpr int NP    = 512;
constexpr int WPB   = 8;
constexpr int NBLK  = NB / WPB;    // 1024
constexpr int DEPTH = 3;           // pipeline slots per warp
constexpr int TILES = 4;           // quarter-batch tiles (128 pts, 96 float4/tensor)

// dynamic smem: [WPB][DEPTH][2 tensors][96 float4] = 8*3*2*96*16 = 73728 B
constexpr int SMEM_BYTES = WPB * DEPTH * 2 * 96 * 16;

__device__ double       g_partial[NBLK];
__device__ unsigned int g_count = 0;

__device__ __forceinline__ unsigned smem_u32(const void* p) {
    return (unsigned)__cvta_generic_to_shared(p);
}
__device__ __forceinline__ void cp16(unsigned dst, const float4* src) {
    asm volatile("cp.async.cg.shared.global [%0], [%1], 16;" :: "r"(dst), "l"(src));
}
__device__ __forceinline__ void cp_commit() {
    asm volatile("cp.async.commit_group;");
}
template <int N>
__device__ __forceinline__ void cp_wait() {
    asm volatile("cp.async.wait_group %0;" :: "n"(N));
}

__device__ __forceinline__ float kabsch_loss(const float* fin)
{
    const float n = (float)NP;
    const float invn = 1.f / n;
    float mx[3], my[3];
#pragma unroll
    for (int d = 0; d < 3; d++) { mx[d] = fin[d] * invn; my[d] = fin[3 + d] * invn; }

    float C[3][3];
#pragma unroll
    for (int d = 0; d < 3; d++)
#pragma unroll
        for (int e = 0; e < 3; e++)
            C[d][e] = fin[8 + 3*d + e] - n * mx[d] * my[e];

    float sxx = fin[6] - n * (mx[0]*mx[0] + mx[1]*mx[1] + mx[2]*mx[2]);
    float syy = fin[7] - n * (my[0]*my[0] + my[1]*my[1] + my[2]*my[2]);

    float a00 = C[0][0]*C[0][0] + C[1][0]*C[1][0] + C[2][0]*C[2][0];
    float a11 = C[0][1]*C[0][1] + C[1][1]*C[1][1] + C[2][1]*C[2][1];
    float a22 = C[0][2]*C[0][2] + C[1][2]*C[1][2] + C[2][2]*C[2][2];
    float a01 = C[0][0]*C[0][1] + C[1][0]*C[1][1] + C[2][0]*C[2][1];
    float a02 = C[0][0]*C[0][2] + C[1][0]*C[1][2] + C[2][0]*C[2][2];
    float a12 = C[0][1]*C[0][2] + C[1][1]*C[1][2] + C[2][1]*C[2][2];

    float q  = (a00 + a11 + a22) * (1.f / 3.f);
    float p1 = a01*a01 + a02*a02 + a12*a12;
    float b00 = a00 - q, b11 = a11 - q, b22 = a22 - q;
    float p2 = b00*b00 + b11*b11 + b22*b22 + 2.f * p1;
    float p  = sqrtf(fmaxf(p2, 1e-30f) * (1.f / 6.f));
    float ip = 1.f / p;
    float detB = ( b00 * (b11*b22 - a12*a12)
                 - a01 * (a01*b22 - a12*a02)
                 + a02 * (a01*a12 - b11*a02) ) * (ip * ip * ip);
    float r = fminf(fmaxf(0.5f * detB, -1.f), 1.f);
    float phi = acosf(r) * (1.f / 3.f);
    float e0 = q + 2.f * p * cosf(phi);
    float e2 = q + 2.f * p * cosf(phi + 2.0943951023931953f);
    float e1 = 3.f * q - e0 - e2;

    float s0 = sqrtf(fmaxf(e0, 0.f));
    float s1 = sqrtf(fmaxf(e1, 0.f));
    float s2 = sqrtf(fmaxf(e2, 0.f));

    float detC = C[0][0]*(C[1][1]*C[2][2] - C[1][2]*C[2][1])
               - C[0][1]*(C[1][0]*C[2][2] - C[1][2]*C[2][0])
               + C[0][2]*(C[1][0]*C[2][1] - C[1][1]*C[2][0]);
    float sgn = (detC < 0.f) ? -1.f : 1.f;

    return sxx + syy - 2.f * (s0 + s1 + sgn * s2);
}

__global__ __launch_bounds__(256)
void rmsd_fused_kernel(const float4* __restrict__ x4, const float4* __restrict__ y4,
                       float* __restrict__ out)
{
    extern __shared__ float4 smem[];   // [WPB][DEPTH][2][96]

    const int w    = threadIdx.x >> 5;
    const int lane = threadIdx.x & 31;
    const int b    = blockIdx.x * WPB + w;
    const size_t base = (size_t)b * 384;     // float4 per batch

    // slot base (in float4) for this warp, stage slot s, tensor ts
    auto slot = [&](int s, int ts) -> float4* {
        return smem + (((w * DEPTH) + s) * 2 + ts) * 96;
    };

    // issue one quarter-tile stage: 3 float4 per lane per tensor
    auto issue = [&](int tile) {
        const int s = tile % DEPTH;
        const size_t tb = base + (size_t)tile * 96;
        unsigned dx = smem_u32(slot(s, 0) + lane);
        unsigned dy = smem_u32(slot(s, 1) + lane);
#pragma unroll
        for (int m = 0; m < 3; m++) {
            cp16(dx + m * 32 * 16, x4 + tb + m * 32 + lane);
            cp16(dy + m * 32 * 16, y4 + tb + m * 32 + lane);
        }
        cp_commit();
    };

    // Prologue: fill the pipeline
    issue(0); issue(1); issue(2);

    float v[17];
#pragma unroll
    for (int i = 0; i < 17; i++) v[i] = 0.f;

    auto compute_tile = [&](int tile) {
        const int s = tile % DEPTH;
        const float* sx = reinterpret_cast<const float*>(slot(s, 0));
        const float* sy = reinterpret_cast<const float*>(slot(s, 1));
#pragma unroll
        for (int c = 0; c < 4; c++) {
            const int p = c * 32 + lane;
            float X[3] = { sx[3*p], sx[3*p + 1], sx[3*p + 2] };
            float Y[3] = { sy[3*p], sy[3*p + 1], sy[3*p + 2] };
#pragma unroll
            for (int d = 0; d < 3; d++) {
                v[d]     += X[d];
                v[3 + d] += Y[d];
                v[6]     += X[d] * X[d];
                v[7]     += Y[d] * Y[d];
#pragma unroll
                for (int e = 0; e < 3; e++)
                    v[8 + 3*d + e] += X[d] * Y[e];
            }
        }
    };

    // tile 0: 3 groups in flight, need group(0) done -> wait_group 2
    cp_wait<2>(); __syncwarp();
    compute_tile(0);
    __syncwarp();          // everyone done with slot 0 before reuse
    issue(3);

    // tile 1: groups pending = {1,2,3}; need group(1) -> wait 2
    cp_wait<2>(); __syncwarp();
    compute_tile(1);

    // tile 2: pending = {2,3}; need group(2) -> wait 1
    cp_wait<1>(); __syncwarp();
    compute_tile(2);

    // tile 3: pending = {3}; -> wait 0
    cp_wait<0>(); __syncwarp();
    compute_tile(3);

    // Warp tree-reduce 17 values
#pragma unroll
    for (int i = 0; i < 17; i++) {
#pragma unroll
        for (int o = 16; o > 0; o >>= 1)
            v[i] += __shfl_down_sync(0xffffffffu, v[i], o);
    }

    __shared__ float warp_loss[WPB];
    __shared__ int   is_last;
    if (lane == 0) warp_loss[w] = kabsch_loss(v);
    __syncthreads();

    if (threadIdx.x == 0) {
        double s = 0.0;
#pragma unroll
        for (int i = 0; i < WPB; i++) s += (double)warp_loss[i];
        g_partial[blockIdx.x] = s;
        __threadfence();
        unsigned done = atomicAdd(&g_count, 1u);
        is_last = (done == NBLK - 1) ? 1 : 0;
    }
    __syncthreads();

    if (is_last) {
        __threadfence();
        const int t = threadIdx.x;
        volatile double* gp = g_partial;
        double s = 0.0;
#pragma unroll
        for (int i = 0; i < NBLK / 256; i++) s += gp[t + i * 256];

#pragma unroll
        for (int o = 16; o > 0; o >>= 1)
            s += __shfl_down_sync(0xffffffffu, s, o);

        __shared__ double sm[8];
        if (lane == 0) sm[w] = s;
        __syncthreads();
        if (t == 0) {
            double tot = 0.0;
#pragma unroll
            for (int i = 0; i < 8; i++) tot += sm[i];
            out[0] = (float)(tot / ((double)NB * (double)NP * 3.0));
            g_count = 0;   // reset for graph replay
        }
    }
}

extern "C" void kernel_launch(void* const* d_in, const int* in_sizes, int n_in,
                              void* d_out, int out_size)
{
    const float4* inp = (const float4*)d_in[0];
    const float4* tgt = (const float4*)d_in[1];
    float* out = (float*)d_out;

    static int configured = 0;
    if (!configured) {
        cudaFuncSetAttribute(rmsd_fused_kernel,
                             cudaFuncAttributeMaxDynamicSharedMemorySize, SMEM_BYTES);
        configured = 1;
    }
    rmsd_fused_kernel<<<NBLK, 256, SMEM_BYTES>>>(inp, tgt, out);
}

// round 6
// speedup vs baseline: 1.2092x; 1.2092x over previous
#include <cuda_runtime.h>
#include <math.h>

// RMSD (Kabsch-aligned MSE). Bulk-copy (TMA/UBLKCP) streaming: one instruction
// per 48KB chunk removes the LSU 16B-per-issue ceiling that capped LDG/cp.async
// variants at ~4.8 TB/s. Persistent 148 CTAs, 8-batch stages, double-buffered.

constexpr int NB      = 8192;
constexpr int GRID    = 148;             // 1 CTA per SM
constexpr int BPS     = 8;               // batches per stage (1 per warp)
constexpr int NSTAGES = NB / BPS;        // 1024 stages
constexpr int BATCH_BYTES = 512 * 3 * 4; // 6144 B per tensor per batch
constexpr int CHUNK  = BPS * BATCH_BYTES;        // 49152 B per tensor per stage
constexpr int STAGE_BYTES = 2 * CHUNK;           // 98304 B
constexpr int SMEM_BYTES  = 2 * STAGE_BYTES;     // 196608 B (double buffer)

__device__ double       g_partial[GRID];
__device__ unsigned int g_count = 0;

__device__ __forceinline__ unsigned smem_u32(const void* p) {
    return (unsigned)__cvta_generic_to_shared(p);
}
__device__ __forceinline__ void bulk_cp(unsigned dst, const void* src, unsigned bytes,
                                        unsigned mbar) {
    asm volatile(
        "cp.async.bulk.shared::cluster.global.mbarrier::complete_tx::bytes "
        "[%0], [%1], %2, [%3];"
        :: "r"(dst), "l"(src), "r"(bytes), "r"(mbar) : "memory");
}
__device__ __forceinline__ void mbar_init(unsigned mbar, unsigned count) {
    asm volatile("mbarrier.init.shared.b64 [%0], %1;" :: "r"(mbar), "r"(count) : "memory");
}
__device__ __forceinline__ void mbar_expect_tx(unsigned mbar, unsigned tx) {
    asm volatile("mbarrier.arrive.expect_tx.shared.b64 _, [%0], %1;"
                 :: "r"(mbar), "r"(tx) : "memory");
}
__device__ __forceinline__ void mbar_wait(unsigned mbar, unsigned parity) {
    asm volatile(
        "{\n\t"
        ".reg .pred P;\n\t"
        "WAIT_%=:\n\t"
        "mbarrier.try_wait.parity.acquire.cta.shared::cta.b64 P, [%0], %1, 0x989680;\n\t"
        "@P bra.uni DONE_%=;\n\t"
        "bra.uni WAIT_%=;\n\t"
        "DONE_%=:\n\t"
        "}"
        :: "r"(mbar), "r"(parity) : "memory");
}

__device__ __forceinline__ float kabsch_loss(const float* fin)
{
    const float n = 512.f;
    const float invn = 1.f / n;
    float mx[3], my[3];
#pragma unroll
    for (int d = 0; d < 3; d++) { mx[d] = fin[d] * invn; my[d] = fin[3 + d] * invn; }

    float C[3][3];
#pragma unroll
    for (int d = 0; d < 3; d++)
#pragma unroll
        for (int e = 0; e < 3; e++)
            C[d][e] = fin[8 + 3*d + e] - n * mx[d] * my[e];

    float sxx = fin[6] - n * (mx[0]*mx[0] + mx[1]*mx[1] + mx[2]*mx[2]);
    float syy = fin[7] - n * (my[0]*my[0] + my[1]*my[1] + my[2]*my[2]);

    float a00 = C[0][0]*C[0][0] + C[1][0]*C[1][0] + C[2][0]*C[2][0];
    float a11 = C[0][1]*C[0][1] + C[1][1]*C[1][1] + C[2][1]*C[2][1];
    float a22 = C[0][2]*C[0][2] + C[1][2]*C[1][2] + C[2][2]*C[2][2];
    float a01 = C[0][0]*C[0][1] + C[1][0]*C[1][1] + C[2][0]*C[2][1];
    float a02 = C[0][0]*C[0][2] + C[1][0]*C[1][2] + C[2][0]*C[2][2];
    float a12 = C[0][1]*C[0][2] + C[1][1]*C[1][2] + C[2][1]*C[2][2];

    float q  = (a00 + a11 + a22) * (1.f / 3.f);
    float p1 = a01*a01 + a02*a02 + a12*a12;
    float b00 = a00 - q, b11 = a11 - q, b22 = a22 - q;
    float p2 = b00*b00 + b11*b11 + b22*b22 + 2.f * p1;
    float p  = sqrtf(fmaxf(p2, 1e-30f) * (1.f / 6.f));
    float ip = 1.f / p;
    float detB = ( b00 * (b11*b22 - a12*a12)
                 - a01 * (a01*b22 - a12*a02)
                 + a02 * (a01*a12 - b11*a02) ) * (ip * ip * ip);
    float r = fminf(fmaxf(0.5f * detB, -1.f), 1.f);
    float phi = acosf(r) * (1.f / 3.f);
    float e0 = q + 2.f * p * cosf(phi);
    float e2 = q + 2.f * p * cosf(phi + 2.0943951023931953f);
    float e1 = 3.f * q - e0 - e2;

    float s0 = sqrtf(fmaxf(e0, 0.f));
    float s1 = sqrtf(fmaxf(e1, 0.f));
    float s2 = sqrtf(fmaxf(e2, 0.f));

    float detC = C[0][0]*(C[1][1]*C[2][2] - C[1][2]*C[2][1])
               - C[0][1]*(C[1][0]*C[2][2] - C[1][2]*C[2][0])
               + C[0][2]*(C[1][0]*C[2][1] - C[1][1]*C[2][0]);
    float sgn = (detC < 0.f) ? -1.f : 1.f;

    return sxx + syy - 2.f * (s0 + s1 + sgn * s2);
}

__global__ __launch_bounds__(256)
void rmsd_fused_kernel(const char* __restrict__ xg, const char* __restrict__ yg,
                       float* __restrict__ out)
{
    extern __shared__ char smem[];            // [2 slots][x 48KB | y 48KB]
    __shared__ unsigned long long mbar_store[2];
    __shared__ double warp_loss[8];
    __shared__ int    is_last;

    const int tid  = threadIdx.x;
    const int w    = tid >> 5;
    const int lane = tid & 31;

    const unsigned mb0 = smem_u32(&mbar_store[0]);
    const unsigned mb1 = smem_u32(&mbar_store[1]);
    const unsigned smem_base = smem_u32(smem);

    if (tid == 0) { mbar_init(mb0, 1); mbar_init(mb1, 1); }
    __syncthreads();

    // Stages for this CTA: s = blockIdx.x + k*GRID, k = 0..total-1
    const int total = (NSTAGES - blockIdx.x + GRID - 1) / GRID;

    auto issue = [&](int k) {                 // local stage index k
        const int stage = blockIdx.x + k * GRID;
        const int slot  = k & 1;
        const unsigned mb = slot ? mb1 : mb0;
        const size_t goff = (size_t)stage * CHUNK;
        mbar_expect_tx(mb, STAGE_BYTES);
        bulk_cp(smem_base + slot * STAGE_BYTES,         xg + goff, CHUNK, mb);
        bulk_cp(smem_base + slot * STAGE_BYTES + CHUNK, yg + goff, CHUNK, mb);
    };

    double local_loss = 0.0;

    if (total > 0 && tid == 0) issue(0);
    __syncthreads();   // issue(0) visible; harmless

    for (int k = 0; k < total; k++) {
        if (k + 1 < total && tid == 0) issue(k + 1);

        const int slot = k & 1;
        mbar_wait(slot ? mb1 : mb0, (k >> 1) & 1);

        // Compute: warp w owns batch (stage*8 + w); data at slot base + w*6144
        const float* sx = reinterpret_cast<const float*>(
            smem + slot * STAGE_BYTES + w * BATCH_BYTES);
        const float* sy = reinterpret_cast<const float*>(
            smem + slot * STAGE_BYTES + CHUNK + w * BATCH_BYTES);

        float v[17];
#pragma unroll
        for (int i = 0; i < 17; i++) v[i] = 0.f;

#pragma unroll
        for (int c = 0; c < 16; c++) {
            const int p = c * 32 + lane;
            float X[3] = { sx[3*p], sx[3*p + 1], sx[3*p + 2] };
            float Y[3] = { sy[3*p], sy[3*p + 1], sy[3*p + 2] };
#pragma unroll
            for (int d = 0; d < 3; d++) {
                v[d]     += X[d];
                v[3 + d] += Y[d];
                v[6]     += X[d] * X[d];
                v[7]     += Y[d] * Y[d];
#pragma unroll
                for (int e = 0; e < 3; e++)
                    v[8 + 3*d + e] += X[d] * Y[e];
            }
        }

#pragma unroll
        for (int i = 0; i < 17; i++) {
#pragma unroll
            for (int o = 16; o > 0; o >>= 1)
                v[i] += __shfl_down_sync(0xffffffffu, v[i], o);
        }

        if (lane == 0) local_loss += (double)kabsch_loss(v);

        __syncthreads();   // all warps done reading this slot before reuse
    }

    if (lane == 0) warp_loss[w] = local_loss;
    __syncthreads();

    if (tid == 0) {
        double s = 0.0;
#pragma unroll
        for (int i = 0; i < 8; i++) s += warp_loss[i];
        g_partial[blockIdx.x] = s;
        __threadfence();
        unsigned done = atomicAdd(&g_count, 1u);
        is_last = (done == GRID - 1) ? 1 : 0;
    }
    __syncthreads();

    if (is_last) {
        __threadfence();
        volatile double* gp = g_partial;
        double s = (tid < GRID) ? gp[tid] : 0.0;

#pragma unroll
        for (int o = 16; o > 0; o >>= 1)
            s += __shfl_down_sync(0xffffffffu, s, o);

        __shared__ double sm[8];
        if (lane == 0) sm[w] = s;
        __syncthreads();
        if (tid == 0) {
            double tot = 0.0;
#pragma unroll
            for (int i = 0; i < 8; i++) tot += sm[i];
            out[0] = (float)(tot / ((double)NB * 512.0 * 3.0));
            g_count = 0;   // reset for graph replay
        }
    }
}

extern "C" void kernel_launch(void* const* d_in, const int* in_sizes, int n_in,
                              void* d_out, int out_size)
{
    const char* inp = (const char*)d_in[0];
    const char* tgt = (const char*)d_in[1];
    float* out = (float*)d_out;

    static int configured = 0;
    if (!configured) {
        cudaFuncSetAttribute(rmsd_fused_kernel,
                             cudaFuncAttributeMaxDynamicSharedMemorySize, SMEM_BYTES);
        configured = 1;
    }
    rmsd_fused_kernel<<<GRID, 256, SMEM_BYTES>>>(inp, tgt, out);
}